// round 1
// baseline (speedup 1.0000x reference)
#include <cuda_runtime.h>
#include <math.h>

#define DIMC    256
#define NHEAD   4
#define HDIM    64
#define VV      3
#define BB      2
#define HH      32
#define WW      32
#define NN      (HH*WW)        // 1024
#define LL      (VV*NN)        // 3072
#define MROWS   (BB*LL)        // 6144
#define SCALE_F 0.125f         // 64^-0.5
#define LNEPS   1e-5f

// ---------------- scratch (static device allocs only) ----------------
__device__ float g_x[MROWS*DIMC];
__device__ float g_q[MROWS*DIMC];
__device__ float g_k[MROWS*DIMC];
__device__ float g_v[MROWS*DIMC];
__device__ float g_o[MROWS*DIMC];
__device__ float g_p[MROWS*DIMC];

// ---------------- 1) pack features (V,B,C,N) -> x[B, L=V*N, C] ----------------
__global__ void pack_x(const float* __restrict__ f) {
    __shared__ float tile[32][33];
    int vb = blockIdx.z;            // v*BB + b
    int v  = vb / BB;
    int b  = vb % BB;
    int n0 = blockIdx.x * 32;
    int c0 = blockIdx.y * 32;
    int tx = threadIdx.x, ty = threadIdx.y;
    // read along n (coalesced)
    tile[ty][tx] = f[((size_t)vb*DIMC + (c0+ty))*NN + n0 + tx];
    __syncthreads();
    // write along c (coalesced)
    g_x[((size_t)(b*LL + v*NN + n0 + ty))*DIMC + c0 + tx] = tile[tx][ty];
}

// ---------------- 2) GEMM: C[m,c] = bias[c] + sum_k A[m,k]*W[c,k] ----------------
// BM=32, BN=256 (full width), BK=32; 256 threads; thread tile 4 rows x 8 cols (cyclic cols)
__global__ void gemm_nt_bias(const float* __restrict__ A,
                             const float* __restrict__ W,
                             const float* __restrict__ bias,
                             float* __restrict__ C) {
    __shared__ float As[32][36];
    __shared__ float Bs[256][33];
    int tid  = threadIdx.x;
    int warp = tid >> 5;      // 0..7
    int tx   = tid & 31;
    int m0   = blockIdx.x * 32;

    float acc[4][8];
#pragma unroll
    for (int i = 0; i < 4; i++)
#pragma unroll
        for (int j = 0; j < 8; j++) acc[i][j] = 0.f;

    for (int kk = 0; kk < 256; kk += 32) {
        {   // A tile: 32x32, float4 per thread
            int row = tid >> 3, col = (tid & 7) * 4;
            float4 a4 = *(const float4*)&A[(size_t)(m0+row)*256 + kk + col];
            As[row][col+0] = a4.x; As[row][col+1] = a4.y;
            As[row][col+2] = a4.z; As[row][col+3] = a4.w;
        }
        // W tile: 256x32, 8 float4 per thread, coalesced
#pragma unroll
        for (int it = 0; it < 8; it++) {
            int p  = tid + it * 256;
            int j  = p >> 3;
            int k4 = (p & 7) * 4;
            float4 w4 = *(const float4*)&W[(size_t)j*256 + kk + k4];
            Bs[j][k4+0] = w4.x; Bs[j][k4+1] = w4.y;
            Bs[j][k4+2] = w4.z; Bs[j][k4+3] = w4.w;
        }
        __syncthreads();
#pragma unroll
        for (int k = 0; k < 32; k++) {
            float a[4], bf[8];
#pragma unroll
            for (int i = 0; i < 4; i++) a[i] = As[warp*4 + i][k];      // broadcast
#pragma unroll
            for (int j = 0; j < 8; j++) bf[j] = Bs[tx + 32*j][k];      // conflict-free
#pragma unroll
            for (int i = 0; i < 4; i++)
#pragma unroll
                for (int j = 0; j < 8; j++) acc[i][j] += a[i] * bf[j];
        }
        __syncthreads();
    }
#pragma unroll
    for (int i = 0; i < 4; i++) {
        int r = m0 + warp*4 + i;
#pragma unroll
        for (int j = 0; j < 8; j++) {
            int c = tx + 32*j;
            C[(size_t)r*256 + c] = acc[i][j] + bias[c];
        }
    }
}

// ---------------- 3) flash attention, fp32 ----------------
// grid (L/64, NHEAD, BB); 256 threads; each warp owns 8 query rows.
__global__ void attn_kernel(const float* __restrict__ Q,
                            const float* __restrict__ K,
                            const float* __restrict__ V,
                            float* __restrict__ O) {
    __shared__ float Qs[64][64];   // [row][d]     (reads are warp-broadcast)
    __shared__ float KP[64][64];   // Kt swizzled [d][c^(d&31)], reused as P [row][c]
    __shared__ float Vs[64][64];   // [row][d]

    int tid  = threadIdx.x;
    int warp = tid >> 5;   // 0..7
    int tx   = tid & 31;
    int q0   = blockIdx.x * 64;
    int h    = blockIdx.y;
    int b    = blockIdx.z;
    const size_t base = ((size_t)b * LL) * DIMC + (size_t)h * HDIM;

    // load Q tile (coalesced)
#pragma unroll
    for (int i = 0; i < 16; i++) {
        int e = tid + 256*i;
        int r = e >> 6, d = e & 63;
        Qs[r][d] = Q[base + (size_t)(q0 + r)*DIMC + d];
    }

    float m[8], l[8], acc[8][2];
#pragma unroll
    for (int i = 0; i < 8; i++) { m[i] = -1e30f; l[i] = 0.f; acc[i][0] = 0.f; acc[i][1] = 0.f; }
    __syncthreads();

    for (int kt = 0; kt < LL; kt += 64) {
        // load K (transposed+swizzled) and V
#pragma unroll
        for (int i = 0; i < 16; i++) {
            int e = tid + 256*i;
            int r = e >> 6, d = e & 63;
            float kv = K[base + (size_t)(kt + r)*DIMC + d];
            KP[d][r ^ (d & 31)] = kv;                       // conflict-free write
            Vs[r][d] = V[base + (size_t)(kt + r)*DIMC + d];
        }
        __syncthreads();

        // gemm1: S = Q Kt   s[i][0] -> col tx, s[i][1] -> col tx+32
        float s[8][2];
#pragma unroll
        for (int i = 0; i < 8; i++) { s[i][0] = 0.f; s[i][1] = 0.f; }
#pragma unroll 4
        for (int d = 0; d < 64; d++) {
            int sw = d & 31;
            float k0 = KP[d][tx ^ sw];
            float k1 = KP[d][(tx ^ sw) + 32];
#pragma unroll
            for (int i = 0; i < 8; i++) {
                float qv = Qs[warp*8 + i][d];
                s[i][0] += qv * k0;
                s[i][1] += qv * k1;
            }
        }

        // online softmax per row (full-warp reductions)
        float p0s[8], p1s[8];
#pragma unroll
        for (int i = 0; i < 8; i++) {
            float sc0 = s[i][0] * SCALE_F;
            float sc1 = s[i][1] * SCALE_F;
            float mt = fmaxf(sc0, sc1);
#pragma unroll
            for (int o = 16; o; o >>= 1) mt = fmaxf(mt, __shfl_xor_sync(0xffffffffu, mt, o));
            float mn = fmaxf(m[i], mt);
            float p0 = __expf(sc0 - mn);
            float p1 = __expf(sc1 - mn);
            float rs = p0 + p1;
#pragma unroll
            for (int o = 16; o; o >>= 1) rs += __shfl_xor_sync(0xffffffffu, rs, o);
            float alpha = __expf(m[i] - mn);
            l[i] = l[i] * alpha + rs;
            m[i] = mn;
            acc[i][0] *= alpha;
            acc[i][1] *= alpha;
            p0s[i] = p0; p1s[i] = p1;
        }
        __syncthreads();          // everyone done reading KP (Kt)
#pragma unroll
        for (int i = 0; i < 8; i++) {
            KP[warp*8 + i][tx]      = p0s[i];   // P tile, natural layout
            KP[warp*8 + i][tx + 32] = p1s[i];
        }
        __syncthreads();

        // gemm2: O += P V
#pragma unroll 4
        for (int k = 0; k < 64; k++) {
            float v0 = Vs[k][tx];
            float v1 = Vs[k][tx + 32];
#pragma unroll
            for (int i = 0; i < 8; i++) {
                float pv = KP[warp*8 + i][k];   // broadcast
                acc[i][0] += pv * v0;
                acc[i][1] += pv * v1;
            }
        }
        __syncthreads();          // before next tile overwrites KP/Vs
    }

#pragma unroll
    for (int i = 0; i < 8; i++) {
        float inv = 1.f / l[i];
        size_t r = q0 + warp*8 + i;
        O[base + r*DIMC + tx]      = acc[i][0] * inv;
        O[base + r*DIMC + tx + 32] = acc[i][1] * inv;
    }
}

// ---------------- 4) output projection + LayerNorm ----------------
__global__ void gemm_ln(const float* __restrict__ A,
                        const float* __restrict__ W,
                        const float* __restrict__ bias,
                        const float* __restrict__ gamma,
                        const float* __restrict__ beta,
                        float* __restrict__ Out) {
    __shared__ float As[32][36];
    __shared__ float Bs[256][33];
    int tid  = threadIdx.x;
    int warp = tid >> 5;
    int tx   = tid & 31;
    int m0   = blockIdx.x * 32;

    float acc[4][8];
#pragma unroll
    for (int i = 0; i < 4; i++)
#pragma unroll
        for (int j = 0; j < 8; j++) acc[i][j] = 0.f;

    for (int kk = 0; kk < 256; kk += 32) {
        {
            int row = tid >> 3, col = (tid & 7) * 4;
            float4 a4 = *(const float4*)&A[(size_t)(m0+row)*256 + kk + col];
            As[row][col+0] = a4.x; As[row][col+1] = a4.y;
            As[row][col+2] = a4.z; As[row][col+3] = a4.w;
        }
#pragma unroll
        for (int it = 0; it < 8; it++) {
            int p  = tid + it * 256;
            int j  = p >> 3;
            int k4 = (p & 7) * 4;
            float4 w4 = *(const float4*)&W[(size_t)j*256 + kk + k4];
            Bs[j][k4+0] = w4.x; Bs[j][k4+1] = w4.y;
            Bs[j][k4+2] = w4.z; Bs[j][k4+3] = w4.w;
        }
        __syncthreads();
#pragma unroll
        for (int k = 0; k < 32; k++) {
            float a[4], bf[8];
#pragma unroll
            for (int i = 0; i < 4; i++) a[i] = As[warp*4 + i][k];
#pragma unroll
            for (int j = 0; j < 8; j++) bf[j] = Bs[tx + 32*j][k];
#pragma unroll
            for (int i = 0; i < 4; i++)
#pragma unroll
                for (int j = 0; j < 8; j++) acc[i][j] += a[i] * bf[j];
        }
        __syncthreads();
    }

    // LayerNorm epilogue: each warp owns rows warp*4..+3 entirely (256 cols over tx,j)
#pragma unroll
    for (int i = 0; i < 4; i++) {
        float rowv[8];
        float sum = 0.f;
#pragma unroll
        for (int j = 0; j < 8; j++) {
            rowv[j] = acc[i][j] + bias[tx + 32*j];
            sum += rowv[j];
        }
#pragma unroll
        for (int o = 16; o; o >>= 1) sum += __shfl_xor_sync(0xffffffffu, sum, o);
        float mu = sum * (1.f/256.f);
        float vs = 0.f;
#pragma unroll
        for (int j = 0; j < 8; j++) { float d = rowv[j] - mu; vs += d * d; }
#pragma unroll
        for (int o = 16; o; o >>= 1) vs += __shfl_xor_sync(0xffffffffu, vs, o);
        float rstd = rsqrtf(vs * (1.f/256.f) + LNEPS);
        size_t r = m0 + warp*4 + i;
#pragma unroll
        for (int j = 0; j < 8; j++) {
            int c = tx + 32*j;
            Out[r*256 + c] = (rowv[j] - mu) * rstd * gamma[c] + beta[c];
        }
    }
}

// ---------------- 5) mean over views + transpose to [B, C, H, W] ----------------
__global__ void mean_views(float* __restrict__ out) {
    __shared__ float tile[32][33];
    int b  = blockIdx.z;
    int n0 = blockIdx.x * 32;
    int c0 = blockIdx.y * 32;
    int tx = threadIdx.x, ty = threadIdx.y;
    float s = 0.f;
#pragma unroll
    for (int v = 0; v < VV; v++)
        s += g_p[((size_t)(b*LL + v*NN + n0 + ty))*DIMC + c0 + tx];
    tile[ty][tx] = s * (1.0f/3.0f);
    __syncthreads();
    out[((size_t)(b*DIMC + c0 + ty))*NN + n0 + tx] = tile[tx][ty];
}

// ---------------- launch ----------------
extern "C" void kernel_launch(void* const* d_in, const int* in_sizes, int n_in,
                              void* d_out, int out_size) {
    const float* f     = (const float*)d_in[0];
    const float* Wq    = (const float*)d_in[1];
    const float* bq    = (const float*)d_in[2];
    const float* Wk    = (const float*)d_in[3];
    const float* bk    = (const float*)d_in[4];
    const float* Wv    = (const float*)d_in[5];
    const float* bv    = (const float*)d_in[6];
    const float* Wp    = (const float*)d_in[7];
    const float* bp    = (const float*)d_in[8];
    const float* gamma = (const float*)d_in[9];
    const float* beta  = (const float*)d_in[10];
    float* out = (float*)d_out;

    float *px, *pq, *pk, *pv, *po;
    cudaGetSymbolAddress((void**)&px, g_x);
    cudaGetSymbolAddress((void**)&pq, g_q);
    cudaGetSymbolAddress((void**)&pk, g_k);
    cudaGetSymbolAddress((void**)&pv, g_v);
    cudaGetSymbolAddress((void**)&po, g_o);
    float *pp;
    cudaGetSymbolAddress((void**)&pp, g_p);

    // 1) pack x
    pack_x<<<dim3(NN/32, DIMC/32, VV*BB), dim3(32,32)>>>(f);
    // 2) QKV projections
    gemm_nt_bias<<<MROWS/32, 256>>>(px, Wq, bq, pq);
    gemm_nt_bias<<<MROWS/32, 256>>>(px, Wk, bk, pk);
    gemm_nt_bias<<<MROWS/32, 256>>>(px, Wv, bv, pv);
    // 3) attention
    attn_kernel<<<dim3(LL/64, NHEAD, BB), 256>>>(pq, pk, pv, po);
    // 4) output projection + LayerNorm
    gemm_ln<<<MROWS/32, 256>>>(po, Wp, bp, gamma, beta, pp);
    // 5) mean over views + transpose
    mean_views<<<dim3(NN/32, DIMC/32, BB), dim3(32,32)>>>(out);
}

// round 2
// speedup vs baseline: 4.1728x; 4.1728x over previous
#include <cuda_runtime.h>
#include <math.h>

#define DIMC    256
#define NHEAD   4
#define HDIM    64
#define VV      3
#define BB      2
#define NN      1024
#define LL      3072           // VV*NN
#define MROWS   6144           // BB*LL
#define SCALE_F 0.125f         // 64^-0.5 (exact power of two)
#define LNEPS   1e-5f

// ---------------- scratch ----------------
__device__ float g_x[MROWS*DIMC];
__device__ float g_q[MROWS*DIMC];
__device__ float g_k[MROWS*DIMC];
__device__ float g_v[MROWS*DIMC];
__device__ float g_o[MROWS*DIMC];
__device__ float g_p[MROWS*DIMC];

__device__ __forceinline__ float to_tf32(float x){
    asm("cvt.rna.tf32.f32 %0, %0;" : "+f"(x));
    return x;
}
__device__ __forceinline__ void mma8(float c[4],
                                     unsigned a0, unsigned a1, unsigned a2, unsigned a3,
                                     unsigned b0, unsigned b1){
    asm volatile("mma.sync.aligned.m16n8k8.row.col.f32.tf32.tf32.f32 "
        "{%0,%1,%2,%3},{%4,%5,%6,%7},{%8,%9},{%0,%1,%2,%3};"
        : "+f"(c[0]),"+f"(c[1]),"+f"(c[2]),"+f"(c[3])
        : "r"(a0),"r"(a1),"r"(a2),"r"(a3),"r"(b0),"r"(b1));
}

// ---------------- 1) pack features (V,B,C,N) -> x[B, L, C], tf32-rounded ----------------
__global__ void pack_x(const float* __restrict__ f) {
    __shared__ float tile[32][33];
    int vb = blockIdx.z;
    int v  = vb / BB, b = vb % BB;
    int n0 = blockIdx.x * 32, c0 = blockIdx.y * 32;
    int tx = threadIdx.x, ty = threadIdx.y;
    tile[ty][tx] = f[((size_t)vb*DIMC + (c0+ty))*NN + n0 + tx];
    __syncthreads();
    g_x[((size_t)(b*LL + v*NN + n0 + ty))*DIMC + c0 + tx] = to_tf32(tile[tx][ty]);
}

// ---------------- 2) fused QKV GEMM (tf32 mma): C[m,n] = bias[n] + A[m,:]·W[n,:] ----------------
// BM=64, BN=128, BK=32; 256 threads; warp grid 2x4; warp tile 32x32
__global__ void gemm_qkv(const float* __restrict__ A,
                         const float* __restrict__ Wq, const float* __restrict__ bq,
                         const float* __restrict__ Wk, const float* __restrict__ bk,
                         const float* __restrict__ Wv, const float* __restrict__ bv) {
    const float* W; const float* bias; float* C;
    if (blockIdx.z == 0)      { W = Wq; bias = bq; C = g_q; }
    else if (blockIdx.z == 1) { W = Wk; bias = bk; C = g_k; }
    else                      { W = Wv; bias = bv; C = g_v; }

    __shared__ float As[64][36];
    __shared__ float Ws[128][36];
    int tid = threadIdx.x;
    int warp = tid >> 5, lane = tid & 31;
    int group = lane >> 2, tig = lane & 3;
    int wm = warp >> 2, wn = warp & 3;
    int m0 = blockIdx.x * 64, n0 = blockIdx.y * 128;

    float acc[2][4][4];
#pragma unroll
    for (int mi = 0; mi < 2; mi++)
#pragma unroll
        for (int nj = 0; nj < 4; nj++)
#pragma unroll
            for (int c = 0; c < 4; c++) acc[mi][nj][c] = 0.f;

    for (int kk = 0; kk < 256; kk += 32) {
#pragma unroll
        for (int i = 0; i < 2; i++) {          // A tile (already tf32-rounded)
            int p = tid + 256*i;
            int r = p >> 3, c4 = (p & 7) * 4;
            float4 a4 = *(const float4*)&A[(size_t)(m0+r)*256 + kk + c4];
            As[r][c4+0]=a4.x; As[r][c4+1]=a4.y; As[r][c4+2]=a4.z; As[r][c4+3]=a4.w;
        }
#pragma unroll
        for (int i = 0; i < 4; i++) {          // W tile (round to tf32 here)
            int p = tid + 256*i;
            int r = p >> 3, c4 = (p & 7) * 4;
            float4 w4 = *(const float4*)&W[(size_t)(n0+r)*256 + kk + c4];
            Ws[r][c4+0]=to_tf32(w4.x); Ws[r][c4+1]=to_tf32(w4.y);
            Ws[r][c4+2]=to_tf32(w4.z); Ws[r][c4+3]=to_tf32(w4.w);
        }
        __syncthreads();
#pragma unroll
        for (int ks = 0; ks < 4; ks++) {
            unsigned a[2][4], b[4][2];
#pragma unroll
            for (int mi = 0; mi < 2; mi++) {
                int mr = wm*32 + mi*16 + group;
                a[mi][0] = __float_as_uint(As[mr  ][ks*8+tig  ]);
                a[mi][1] = __float_as_uint(As[mr+8][ks*8+tig  ]);
                a[mi][2] = __float_as_uint(As[mr  ][ks*8+tig+4]);
                a[mi][3] = __float_as_uint(As[mr+8][ks*8+tig+4]);
            }
#pragma unroll
            for (int nj = 0; nj < 4; nj++) {
                int nr = wn*32 + nj*8 + group;
                b[nj][0] = __float_as_uint(Ws[nr][ks*8+tig  ]);
                b[nj][1] = __float_as_uint(Ws[nr][ks*8+tig+4]);
            }
#pragma unroll
            for (int mi = 0; mi < 2; mi++)
#pragma unroll
                for (int nj = 0; nj < 4; nj++)
                    mma8(acc[mi][nj], a[mi][0],a[mi][1],a[mi][2],a[mi][3], b[nj][0],b[nj][1]);
        }
        __syncthreads();
    }
#pragma unroll
    for (int mi = 0; mi < 2; mi++) {
        int r0 = m0 + wm*32 + mi*16 + group;
#pragma unroll
        for (int nj = 0; nj < 4; nj++) {
            int c = n0 + wn*32 + nj*8 + 2*tig;
            float b0v = bias[c], b1v = bias[c+1];
            float2 v0 = make_float2(to_tf32(acc[mi][nj][0]+b0v), to_tf32(acc[mi][nj][1]+b1v));
            float2 v1 = make_float2(to_tf32(acc[mi][nj][2]+b0v), to_tf32(acc[mi][nj][3]+b1v));
            *(float2*)&C[(size_t)r0*256 + c]     = v0;
            *(float2*)&C[(size_t)(r0+8)*256 + c] = v1;
        }
    }
}

// ---------------- 3) flash attention with tf32 mma ----------------
// 128 threads (4 warps); block = 64 queries; warp owns 16 query rows.
__global__ void attn_mma(const float* __restrict__ Q, const float* __restrict__ K,
                         const float* __restrict__ V, float* __restrict__ O) {
    __shared__ float KP[64][68];   // K tile [key][d], then P tile [qrow][key]
    __shared__ float Vs[64][72];   // V tile [key][d]
    int tid  = threadIdx.x;
    int warp = tid >> 5, lane = tid & 31;
    int group = lane >> 2, tig = lane & 3;
    int q0 = blockIdx.x * 64;
    int h  = blockIdx.y, b = blockIdx.z;
    const size_t base = ((size_t)b * LL) * DIMC + (size_t)h * HDIM;
    int mr = warp*16 + group;

    // stage Q through KP, build A-fragments (fold SCALE_F: exact pow2, stays tf32)
#pragma unroll
    for (int i = 0; i < 8; i++) {
        int p = tid + 128*i;
        int r = p >> 4, c4 = (p & 15) * 4;
        *(float4*)&KP[r][c4] = *(const float4*)&Q[base + (size_t)(q0+r)*256 + c4];
    }
    __syncthreads();
    unsigned qf[8][4];
#pragma unroll
    for (int ks = 0; ks < 8; ks++) {
        qf[ks][0] = __float_as_uint(KP[mr  ][ks*8+tig  ] * SCALE_F);
        qf[ks][1] = __float_as_uint(KP[mr+8][ks*8+tig  ] * SCALE_F);
        qf[ks][2] = __float_as_uint(KP[mr  ][ks*8+tig+4] * SCALE_F);
        qf[ks][3] = __float_as_uint(KP[mr+8][ks*8+tig+4] * SCALE_F);
    }
    __syncthreads();

    float m0v = -1e30f, m1v = -1e30f, l0 = 0.f, l1 = 0.f;
    float o[8][4];
#pragma unroll
    for (int nj = 0; nj < 8; nj++)
#pragma unroll
        for (int c = 0; c < 4; c++) o[nj][c] = 0.f;

    for (int kt = 0; kt < LL; kt += 64) {
#pragma unroll
        for (int i = 0; i < 8; i++) {
            int p = tid + 128*i;
            int r = p >> 4, c4 = (p & 15) * 4;
            *(float4*)&KP[r][c4] = *(const float4*)&K[base + (size_t)(kt+r)*256 + c4];
            *(float4*)&Vs[r][c4] = *(const float4*)&V[base + (size_t)(kt+r)*256 + c4];
        }
        __syncthreads();

        // S = (Q*scale) Kt
        float s[8][4];
#pragma unroll
        for (int nj = 0; nj < 8; nj++)
#pragma unroll
            for (int c = 0; c < 4; c++) s[nj][c] = 0.f;
#pragma unroll
        for (int ks = 0; ks < 8; ks++)
#pragma unroll
            for (int nj = 0; nj < 8; nj++) {
                unsigned b0 = __float_as_uint(KP[nj*8+group][ks*8+tig  ]);
                unsigned b1 = __float_as_uint(KP[nj*8+group][ks*8+tig+4]);
                mma8(s[nj], qf[ks][0],qf[ks][1],qf[ks][2],qf[ks][3], b0,b1);
            }

        // online softmax (rows: mr -> c0,c1 ; mr+8 -> c2,c3); group-of-4 shfl reduce
        float mx0 = -1e30f, mx1 = -1e30f;
#pragma unroll
        for (int nj = 0; nj < 8; nj++) {
            mx0 = fmaxf(mx0, fmaxf(s[nj][0], s[nj][1]));
            mx1 = fmaxf(mx1, fmaxf(s[nj][2], s[nj][3]));
        }
        mx0 = fmaxf(mx0, __shfl_xor_sync(0xffffffffu, mx0, 1));
        mx0 = fmaxf(mx0, __shfl_xor_sync(0xffffffffu, mx0, 2));
        mx1 = fmaxf(mx1, __shfl_xor_sync(0xffffffffu, mx1, 1));
        mx1 = fmaxf(mx1, __shfl_xor_sync(0xffffffffu, mx1, 2));
        float mn0 = fmaxf(m0v, mx0), mn1 = fmaxf(m1v, mx1);
        float sum0 = 0.f, sum1 = 0.f;
#pragma unroll
        for (int nj = 0; nj < 8; nj++) {
            s[nj][0] = __expf(s[nj][0] - mn0);
            s[nj][1] = __expf(s[nj][1] - mn0);
            s[nj][2] = __expf(s[nj][2] - mn1);
            s[nj][3] = __expf(s[nj][3] - mn1);
            sum0 += s[nj][0] + s[nj][1];
            sum1 += s[nj][2] + s[nj][3];
        }
        sum0 += __shfl_xor_sync(0xffffffffu, sum0, 1);
        sum0 += __shfl_xor_sync(0xffffffffu, sum0, 2);
        sum1 += __shfl_xor_sync(0xffffffffu, sum1, 1);
        sum1 += __shfl_xor_sync(0xffffffffu, sum1, 2);
        float a0 = __expf(m0v - mn0), a1 = __expf(m1v - mn1);
        l0 = l0*a0 + sum0;  l1 = l1*a1 + sum1;
        m0v = mn0;          m1v = mn1;
#pragma unroll
        for (int nj = 0; nj < 8; nj++) {
            o[nj][0] *= a0; o[nj][1] *= a0;
            o[nj][2] *= a1; o[nj][3] *= a1;
        }

        __syncthreads();             // all warps done reading K tile
        // store P into KP (warp-private rows), tf32-rounded
#pragma unroll
        for (int nj = 0; nj < 8; nj++) {
            int c = nj*8 + 2*tig;
            *(float2*)&KP[mr  ][c] = make_float2(to_tf32(s[nj][0]), to_tf32(s[nj][1]));
            *(float2*)&KP[mr+8][c] = make_float2(to_tf32(s[nj][2]), to_tf32(s[nj][3]));
        }
        __syncwarp();

        // O += P V
#pragma unroll
        for (int ks = 0; ks < 8; ks++) {
            unsigned a0u = __float_as_uint(KP[mr  ][ks*8+tig  ]);
            unsigned a1u = __float_as_uint(KP[mr+8][ks*8+tig  ]);
            unsigned a2u = __float_as_uint(KP[mr  ][ks*8+tig+4]);
            unsigned a3u = __float_as_uint(KP[mr+8][ks*8+tig+4]);
#pragma unroll
            for (int nj = 0; nj < 8; nj++) {
                unsigned b0 = __float_as_uint(Vs[ks*8+tig  ][nj*8+group]);
                unsigned b1 = __float_as_uint(Vs[ks*8+tig+4][nj*8+group]);
                mma8(o[nj], a0u,a1u,a2u,a3u, b0,b1);
            }
        }
        __syncthreads();             // before next tile overwrites KP/Vs
    }

    float inv0 = 1.f/l0, inv1 = 1.f/l1;
    size_t r0 = q0 + mr, r1 = r0 + 8;
#pragma unroll
    for (int nj = 0; nj < 8; nj++) {
        int c = nj*8 + 2*tig;
        *(float2*)&O[base + r0*256 + c] = make_float2(to_tf32(o[nj][0]*inv0), to_tf32(o[nj][1]*inv0));
        *(float2*)&O[base + r1*256 + c] = make_float2(to_tf32(o[nj][2]*inv1), to_tf32(o[nj][3]*inv1));
    }
}

// ---------------- 4) output projection (tf32 mma) + fused LayerNorm ----------------
// BM=64, BN=256 (full width); 8 warps: wm(2) x wn(4); warp tile 32x64
__global__ void gemm_p_ln(const float* __restrict__ A, const float* __restrict__ W,
                          const float* __restrict__ bias, const float* __restrict__ gamma,
                          const float* __restrict__ beta, float* __restrict__ Out) {
    __shared__ float As[64][36];
    __shared__ float Ws[256][36];
    __shared__ float psum[64][4];
    __shared__ float psq[64][4];
    int tid = threadIdx.x;
    int warp = tid >> 5, lane = tid & 31;
    int group = lane >> 2, tig = lane & 3;
    int wm = warp >> 2, wn = warp & 3;
    int m0 = blockIdx.x * 64;

    float acc[2][8][4];
#pragma unroll
    for (int mi = 0; mi < 2; mi++)
#pragma unroll
        for (int nj = 0; nj < 8; nj++)
#pragma unroll
            for (int c = 0; c < 4; c++) acc[mi][nj][c] = 0.f;

    for (int kk = 0; kk < 256; kk += 32) {
#pragma unroll
        for (int i = 0; i < 2; i++) {
            int p = tid + 256*i;
            int r = p >> 3, c4 = (p & 7) * 4;
            float4 a4 = *(const float4*)&A[(size_t)(m0+r)*256 + kk + c4];
            As[r][c4+0]=a4.x; As[r][c4+1]=a4.y; As[r][c4+2]=a4.z; As[r][c4+3]=a4.w;
        }
#pragma unroll
        for (int i = 0; i < 8; i++) {
            int p = tid + 256*i;
            int r = p >> 3, c4 = (p & 7) * 4;
            float4 w4 = *(const float4*)&W[(size_t)r*256 + kk + c4];
            Ws[r][c4+0]=to_tf32(w4.x); Ws[r][c4+1]=to_tf32(w4.y);
            Ws[r][c4+2]=to_tf32(w4.z); Ws[r][c4+3]=to_tf32(w4.w);
        }
        __syncthreads();
#pragma unroll
        for (int ks = 0; ks < 4; ks++) {
            unsigned a[2][4];
#pragma unroll
            for (int mi = 0; mi < 2; mi++) {
                int mrr = wm*32 + mi*16 + group;
                a[mi][0] = __float_as_uint(As[mrr  ][ks*8+tig  ]);
                a[mi][1] = __float_as_uint(As[mrr+8][ks*8+tig  ]);
                a[mi][2] = __float_as_uint(As[mrr  ][ks*8+tig+4]);
                a[mi][3] = __float_as_uint(As[mrr+8][ks*8+tig+4]);
            }
#pragma unroll
            for (int nj = 0; nj < 8; nj++) {
                int nr = wn*64 + nj*8 + group;
                unsigned b0 = __float_as_uint(Ws[nr][ks*8+tig  ]);
                unsigned b1 = __float_as_uint(Ws[nr][ks*8+tig+4]);
#pragma unroll
                for (int mi = 0; mi < 2; mi++)
                    mma8(acc[mi][nj], a[mi][0],a[mi][1],a[mi][2],a[mi][3], b0,b1);
            }
        }
        __syncthreads();
    }

    // bias + per-row partial stats over this warp's 64 columns
    float rs[2][2], rq[2][2];
#pragma unroll
    for (int mi = 0; mi < 2; mi++) { rs[mi][0]=rs[mi][1]=rq[mi][0]=rq[mi][1]=0.f; }
#pragma unroll
    for (int mi = 0; mi < 2; mi++)
#pragma unroll
        for (int nj = 0; nj < 8; nj++) {
            int c = wn*64 + nj*8 + 2*tig;
            float b0v = bias[c], b1v = bias[c+1];
            acc[mi][nj][0] += b0v; acc[mi][nj][1] += b1v;
            acc[mi][nj][2] += b0v; acc[mi][nj][3] += b1v;
            rs[mi][0] += acc[mi][nj][0] + acc[mi][nj][1];
            rq[mi][0] += acc[mi][nj][0]*acc[mi][nj][0] + acc[mi][nj][1]*acc[mi][nj][1];
            rs[mi][1] += acc[mi][nj][2] + acc[mi][nj][3];
            rq[mi][1] += acc[mi][nj][2]*acc[mi][nj][2] + acc[mi][nj][3]*acc[mi][nj][3];
        }
#pragma unroll
    for (int mi = 0; mi < 2; mi++)
#pragma unroll
        for (int hf = 0; hf < 2; hf++) {
            rs[mi][hf] += __shfl_xor_sync(0xffffffffu, rs[mi][hf], 1);
            rs[mi][hf] += __shfl_xor_sync(0xffffffffu, rs[mi][hf], 2);
            rq[mi][hf] += __shfl_xor_sync(0xffffffffu, rq[mi][hf], 1);
            rq[mi][hf] += __shfl_xor_sync(0xffffffffu, rq[mi][hf], 2);
        }
    if (tig == 0) {
#pragma unroll
        for (int mi = 0; mi < 2; mi++) {
            int lr = wm*32 + mi*16 + group;
            psum[lr][wn]   = rs[mi][0];  psq[lr][wn]   = rq[mi][0];
            psum[lr+8][wn] = rs[mi][1];  psq[lr+8][wn] = rq[mi][1];
        }
    }
    __syncthreads();
#pragma unroll
    for (int mi = 0; mi < 2; mi++)
#pragma unroll
        for (int hf = 0; hf < 2; hf++) {
            int lr = wm*32 + mi*16 + group + hf*8;
            float S = psum[lr][0] + psum[lr][1] + psum[lr][2] + psum[lr][3];
            float Qs2 = psq[lr][0] + psq[lr][1] + psq[lr][2] + psq[lr][3];
            float mu = S * (1.f/256.f);
            float var = Qs2 * (1.f/256.f) - mu*mu;
            float rstd = rsqrtf(var + LNEPS);
            size_t r = m0 + lr;
#pragma unroll
            for (int nj = 0; nj < 8; nj++) {
                int c = wn*64 + nj*8 + 2*tig;
                float v0 = acc[mi][nj][hf*2+0], v1 = acc[mi][nj][hf*2+1];
                float2 w2 = make_float2((v0-mu)*rstd*gamma[c]   + beta[c],
                                        (v1-mu)*rstd*gamma[c+1] + beta[c+1]);
                *(float2*)&Out[r*256 + c] = w2;
            }
        }
}

// ---------------- 5) mean over views + transpose to [B, C, H, W] ----------------
__global__ void mean_views(float* __restrict__ out) {
    __shared__ float tile[32][33];
    int b  = blockIdx.z;
    int n0 = blockIdx.x * 32, c0 = blockIdx.y * 32;
    int tx = threadIdx.x, ty = threadIdx.y;
    float s = 0.f;
#pragma unroll
    for (int v = 0; v < VV; v++)
        s += g_p[((size_t)(b*LL + v*NN + n0 + ty))*DIMC + c0 + tx];
    tile[ty][tx] = s * (1.0f/3.0f);
    __syncthreads();
    out[((size_t)(b*DIMC + c0 + ty))*NN + n0 + tx] = tile[tx][ty];
}

// ---------------- launch ----------------
extern "C" void kernel_launch(void* const* d_in, const int* in_sizes, int n_in,
                              void* d_out, int out_size) {
    const float* f     = (const float*)d_in[0];
    const float* Wq    = (const float*)d_in[1];
    const float* bq    = (const float*)d_in[2];
    const float* Wk    = (const float*)d_in[3];
    const float* bk    = (const float*)d_in[4];
    const float* Wv    = (const float*)d_in[5];
    const float* bv    = (const float*)d_in[6];
    const float* Wp    = (const float*)d_in[7];
    const float* bp    = (const float*)d_in[8];
    const float* gamma = (const float*)d_in[9];
    const float* beta  = (const float*)d_in[10];
    float* out = (float*)d_out;

    float *px, *pq, *pk, *pv, *po, *pp;
    cudaGetSymbolAddress((void**)&px, g_x);
    cudaGetSymbolAddress((void**)&pq, g_q);
    cudaGetSymbolAddress((void**)&pk, g_k);
    cudaGetSymbolAddress((void**)&pv, g_v);
    cudaGetSymbolAddress((void**)&po, g_o);
    cudaGetSymbolAddress((void**)&pp, g_p);

    pack_x<<<dim3(NN/32, DIMC/32, VV*BB), dim3(32,32)>>>(f);
    gemm_qkv<<<dim3(MROWS/64, 2, 3), 256>>>(px, Wq, bq, Wk, bk, Wv, bv);
    attn_mma<<<dim3(LL/64, NHEAD, BB), 128>>>(pq, pk, pv, po);
    gemm_p_ln<<<MROWS/64, 256>>>(po, Wp, bp, gamma, beta, pp);
    mean_views<<<dim3(NN/32, DIMC/32, BB), dim3(32,32)>>>(out);
}